// round 14
// baseline (speedup 1.0000x reference)
#include <cuda_runtime.h>
#include <cstdint>

#define T_SEQ 128
#define BATCH 512
#define DIM   128
#define NQ    8
#define NCH   32   // 4 gates * 8 wires

typedef unsigned long long u64;

__device__ __forceinline__ float tanh_approx(float x) {
    float r;
    asm("tanh.approx.f32 %0, %1;" : "=f"(r) : "f"(x));
    return r;
}
__device__ __forceinline__ void ffma2(u64& acc, u64 a, u64 b) {
    asm("fma.rn.f32x2 %0, %1, %2, %0;" : "+l"(acc) : "l"(a), "l"(b));
}
__device__ __forceinline__ u64 pack2(float lo, float hi) {
    u64 r; asm("mov.b64 %0, {%1, %2};" : "=l"(r) : "f"(lo), "f"(hi)); return r;
}

// smem layout (dynamic):
//   zs : float[4][T_SEQ*32]   @ 0        (64 KB)  z for the block's 4 rows
//   ws : float[128][32]       @ 65536    (16 KB)  Wx staged
//   xs : float[32][129]       @ 81920    (16.5 KB) x staging tile
#define SMEM_ZS 0
#define SMEM_WS 65536
#define SMEM_XS (65536 + 16384)
#define SMEM_TOTAL (65536 + 16384 + 32 * 129 * 4)

// ---------------------------------------------------------------------------
// Single fused kernel, 128 blocks x 128 threads; block owns 4 batch rows.
// Phase 1: the PROVEN GEMM body, run 4x (pass p = timestep quarter), all 4
//   warps cooperating; gemm-row i of a pass = (t = 32p + i/4, row = row0 + i%4).
//   Results land in zs (smem) instead of gmem.
// Phase 2: the PROVEN R4 recurrence, one warp per row, z read from smem.
// Quantum layer (analytic): <Z_w> = prod_{k<=w} cos(phi_k) (w>=1),
//                           <Z_0> = prod_{k=1..7} cos(phi_k).
// ---------------------------------------------------------------------------
__global__ void __launch_bounds__(128) qlstm_fused(
    const float* __restrict__ x,
    const float* __restrict__ Wf, const float* __restrict__ bf, const float* __restrict__ thf,
    const float* __restrict__ Wi, const float* __restrict__ bi, const float* __restrict__ thi,
    const float* __restrict__ Wu, const float* __restrict__ bu, const float* __restrict__ thu,
    const float* __restrict__ Wo, const float* __restrict__ bo, const float* __restrict__ tho,
    float* __restrict__ out)
{
    extern __shared__ __align__(16) char smem_raw[];
    float* zs = reinterpret_cast<float*>(smem_raw + SMEM_ZS);          // [4][128*32]
    float (*ws)[32]  = reinterpret_cast<float(*)[32]>(smem_raw + SMEM_WS);
    float (*xs)[129] = reinterpret_cast<float(*)[129]>(smem_raw + SMEM_XS);

    const int tid  = threadIdx.x;
    const int lane = tid & 31;
    const int warp = tid >> 5;
    const int row0 = blockIdx.x * 4;

    // ===================== Phase 1: x-projection (proven GEMM body) ==========
    {
        // Stage Wx once: ws[k][gate*8+wire]
        #pragma unroll 4
        for (int i = tid; i < 128 * 32; i += 128) {
            int k = i >> 5, j = i & 31;
            int g = j >> 3, w = j & 7;
            const float* Wg = (g == 0) ? Wf : (g == 1) ? Wi : (g == 2) ? Wu : Wo;
            ws[k][j] = Wg[k * 8 + w];
        }

        const int c0 = (tid >> 5) * 8;      // warp-uniform column group

        for (int p = 0; p < 4; ++p) {        // timestep quarter
            u64 acc[4][4];
            #pragma unroll
            for (int r = 0; r < 4; r++)
                #pragma unroll
                for (int q = 0; q < 4; q++) acc[r][q] = 0ull;

            for (int kc = 0; kc < 4; ++kc) {
                __syncthreads();
                // stage 128 gemm-rows x 32 k values (coalesced per warp)
                #pragma unroll 4
                for (int i = tid; i < 128 * 32; i += 128) {
                    int r = i >> 5, kk = i & 31;
                    int t  = p * 32 + (r >> 2);
                    int br = row0 + (r & 3);
                    xs[kk][r] = x[((size_t)t * BATCH + br) * DIM + kc * 32 + kk];
                }
                __syncthreads();

                #pragma unroll
                for (int k = 0; k < 32; ++k) {
                    float xv0 = xs[k][lane      ];
                    float xv1 = xs[k][lane + 32 ];
                    float xv2 = xs[k][lane + 64 ];
                    float xv3 = xs[k][lane + 96 ];
                    u64 xx0 = pack2(xv0, xv0);
                    u64 xx1 = pack2(xv1, xv1);
                    u64 xx2 = pack2(xv2, xv2);
                    u64 xx3 = pack2(xv3, xv3);
                    const u64* wk = reinterpret_cast<const u64*>(&ws[kc * 32 + k][c0]);
                    u64 w0 = wk[0], w1 = wk[1], w2 = wk[2], w3 = wk[3];
                    ffma2(acc[0][0], xx0, w0); ffma2(acc[0][1], xx0, w1);
                    ffma2(acc[0][2], xx0, w2); ffma2(acc[0][3], xx0, w3);
                    ffma2(acc[1][0], xx1, w0); ffma2(acc[1][1], xx1, w1);
                    ffma2(acc[1][2], xx1, w2); ffma2(acc[1][3], xx1, w3);
                    ffma2(acc[2][0], xx2, w0); ffma2(acc[2][1], xx2, w1);
                    ffma2(acc[2][2], xx2, w2); ffma2(acc[2][3], xx2, w3);
                    ffma2(acc[3][0], xx3, w0); ffma2(acc[3][1], xx3, w1);
                    ffma2(acc[3][2], xx3, w2); ffma2(acc[3][3], xx3, w3);
                }
            }

            // epilogue: acc -> zs[rloc][t*32 + c0 ..]
            #pragma unroll
            for (int rr = 0; rr < 4; ++rr) {
                int r = lane + 32 * rr;
                int tl = r >> 2, rloc = r & 3;
                u64* dst = reinterpret_cast<u64*>(
                    zs + rloc * (T_SEQ * NCH) + (p * 32 + tl) * NCH + c0);
                dst[0] = acc[rr][0]; dst[1] = acc[rr][1];
                dst[2] = acc[rr][2]; dst[3] = acc[rr][3];
            }
        }
    }
    __syncthreads();

    // ===================== Phase 2: recurrence (proven R4 body) ==============
    const int row  = row0 + warp;                 // 0..511
    const int gate = lane >> 3;
    const int wire = lane & 7;
    const int base = lane & 24;                    // gate*8

    const float* Wg = (gate == 0) ? Wf : (gate == 1) ? Wi : (gate == 2) ? Wu : Wo;
    const float* bg = (gate == 0) ? bf : (gate == 1) ? bi : (gate == 2) ? bu : bo;
    const float* tg = (gate == 0) ? thf : (gate == 1) ? thi : (gate == 2) ? thu : tho;

    float wh0 = Wg[(DIM + 0) * NQ + wire];
    float wh1 = Wg[(DIM + 1) * NQ + wire];
    float wh2 = Wg[(DIM + 2) * NQ + wire];
    float wh3 = Wg[(DIM + 3) * NQ + wire];
    float wh4 = Wg[(DIM + 4) * NQ + wire];
    float wh5 = Wg[(DIM + 5) * NQ + wire];
    float wh6 = Wg[(DIM + 6) * NQ + wire];
    float wh7 = Wg[(DIM + 7) * NQ + wire];

    const float cbias = bg[wire] + tg[wire];
    const bool  isU   = (gate == 2);
    const float aScl  = isU ? 1.0f : 0.5f;
    const float aMul  = isU ? 1.0f : 0.5f;
    const float aAdd  = isU ? 0.0f : 0.5f;

    const bool p0 = (wire & 1) != 0;
    const bool p1 = (wire & 2) != 0;
    const bool p2 = (wire & 4) != 0;

    float h0=0,h1=0,h2=0,h3=0,h4=0,h5=0,h6=0,h7=0;
    float cstate = 0.0f;

    const float* zr = zs + warp * (T_SEQ * NCH) + lane;
    float znext = zr[0];

    float* outw = out + (size_t)row * NQ + wire;   // step stride = BATCH*NQ

    const unsigned FULL = 0xffffffffu;

    #pragma unroll 2
    for (int t = 0; t < T_SEQ; ++t) {
        float zb = znext + cbias;
        int tn = (t + 1 < T_SEQ) ? (t + 1) : (T_SEQ - 1);
        znext = zr[tn * NCH];                       // smem prefetch (lat 29)

        // z = zb + h . wh  (mul + add tree)
        float m0 = h0*wh0, m1 = h1*wh1, m2 = h2*wh2, m3 = h3*wh3;
        float m4 = h4*wh4, m5 = h5*wh5, m6 = h6*wh6, m7 = h7*wh7;
        float a01 = m0+m1, a23 = m2+m3, a45 = m4+m5, a67 = m6+m7;
        float z = ((a01+a23) + (a45+a67)) + zb;

        float c = __cosf(z);

        // allgather segment cosines (8 independent shfls, 1 level)
        float cc0 = __shfl_sync(FULL, c, base + 0);
        float cc1 = __shfl_sync(FULL, c, base + 1);
        float cc2 = __shfl_sync(FULL, c, base + 2);
        float cc3 = __shfl_sync(FULL, c, base + 3);
        float cc4 = __shfl_sync(FULL, c, base + 4);
        float cc5 = __shfl_sync(FULL, c, base + 5);
        float cc6 = __shfl_sync(FULL, c, base + 6);
        float cc7 = __shfl_sync(FULL, c, base + 7);

        // prefix products (Sklansky)
        float m01 = cc0*cc1, m23 = cc2*cc3, m45 = cc4*cc5, m67 = cc6*cc7;
        float m0123 = m01*m23, m4567 = m45*m67;
        float P1 = m01;
        float P2 = m01*cc2;
        float P3 = m0123;
        float P4 = m0123*cc4;
        float P5 = m0123*m45;
        float P6 = m0123*(m45*cc6);
        float P7 = m0123*m4567;
        float E0 = (cc1*m23)*m4567;          // prod c1..c7

        // mux by wire bits
        float t0v = p0 ? P1 : E0;
        float t1v = p0 ? P3 : P2;
        float t2v = p0 ? P5 : P4;
        float t3v = p0 ? P7 : P6;
        float u0 = p1 ? t1v : t0v;
        float u1 = p1 ? t3v : t2v;
        float e  = p2 ? u1 : u0;             // <Z_wire>

        // activation: sigmoid via tanh for f,i,o; tanh for u
        float act = fmaf(aMul, tanh_approx(e * aScl), aAdd);

        // gather the four gate values of this wire (4 independent shfls)
        float fv = __shfl_sync(FULL, act, wire);
        float iv = __shfl_sync(FULL, act, wire + 8);
        float gv = __shfl_sync(FULL, act, wire + 16);
        float ov = __shfl_sync(FULL, act, wire + 24);

        cstate   = fmaf(fv, cstate, iv * gv);
        float hw = ov * tanh_approx(cstate);

        if (lane < 8)
            outw[(size_t)t * (BATCH * NQ)] = hw;     // predicated store

        // broadcast new hx (8 independent shfls)
        h0 = __shfl_sync(FULL, hw, 0);
        h1 = __shfl_sync(FULL, hw, 1);
        h2 = __shfl_sync(FULL, hw, 2);
        h3 = __shfl_sync(FULL, hw, 3);
        h4 = __shfl_sync(FULL, hw, 4);
        h5 = __shfl_sync(FULL, hw, 5);
        h6 = __shfl_sync(FULL, hw, 6);
        h7 = __shfl_sync(FULL, hw, 7);
    }

    if (lane < 8) {
        const size_t outs_sz = (size_t)T_SEQ * BATCH * NQ;
        float hmy = (wire==0)?h0:(wire==1)?h1:(wire==2)?h2:(wire==3)?h3:
                    (wire==4)?h4:(wire==5)?h5:(wire==6)?h6:h7;
        out[outs_sz + (size_t)row * NQ + wire] = hmy;                          // final hx
        out[outs_sz + (size_t)BATCH * NQ + (size_t)row * NQ + wire] = cstate;  // final cx
    }
}

// ---------------------------------------------------------------------------
// Launch — one kernel, 128 blocks x 128 threads, ~96 KB dynamic smem.
// ---------------------------------------------------------------------------
extern "C" void kernel_launch(void* const* d_in, const int* in_sizes, int n_in,
                              void* d_out, int out_size)
{
    const float* x   = (const float*)d_in[0];
    const float* Wf  = (const float*)d_in[1];
    const float* bf  = (const float*)d_in[2];
    const float* thf = (const float*)d_in[3];
    const float* Wi  = (const float*)d_in[4];
    const float* bi  = (const float*)d_in[5];
    const float* thi = (const float*)d_in[6];
    const float* Wu  = (const float*)d_in[7];
    const float* bu  = (const float*)d_in[8];
    const float* thu = (const float*)d_in[9];
    const float* Wo  = (const float*)d_in[10];
    const float* bo  = (const float*)d_in[11];
    const float* tho = (const float*)d_in[12];
    float* out = (float*)d_out;

    static bool attr_set = false;
    if (!attr_set) {
        cudaFuncSetAttribute(qlstm_fused,
                             cudaFuncAttributeMaxDynamicSharedMemorySize,
                             SMEM_TOTAL);
        attr_set = true;
    }

    qlstm_fused<<<BATCH / 4, 128, SMEM_TOTAL>>>(x,
                                                Wf, bf, thf, Wi, bi, thi,
                                                Wu, bu, thu, Wo, bo, tho, out);
}

// round 16
// speedup vs baseline: 1.5220x; 1.5220x over previous
#include <cuda_runtime.h>
#include <cstdint>

#define T_SEQ 128
#define BATCH 512
#define DIM   128
#define NQ    8
#define NCH   32   // 4 gates * 8 wires

typedef unsigned long long u64;

// Scratch: zpre[(t*BATCH+b)*32 + ch] = x_t[b] @ Wx[:,ch], ch = gate*8+wire
__device__ float g_zpre[(size_t)T_SEQ * BATCH * NCH];

__device__ __forceinline__ float tanh_approx(float x) {
    float r;
    asm("tanh.approx.f32 %0, %1;" : "=f"(r) : "f"(x));
    return r;
}
__device__ __forceinline__ void ffma2(u64& acc, u64 a, u64 b) {
    asm("fma.rn.f32x2 %0, %1, %2, %0;" : "+l"(acc) : "l"(a), "l"(b));
}
__device__ __forceinline__ u64 pack2(float lo, float hi) {
    u64 r; asm("mov.b64 %0, {%1, %2};" : "=l"(r) : "f"(lo), "f"(hi)); return r;
}

// ---------------------------------------------------------------------------
// Kernel A (R4 verbatim, proven): zpre = X @ Wx via packed f32x2 FMA.
// ---------------------------------------------------------------------------
__global__ void __launch_bounds__(128) qlstm_gemm(
    const float* __restrict__ x,
    const float* __restrict__ Wf, const float* __restrict__ Wi,
    const float* __restrict__ Wu, const float* __restrict__ Wo)
{
    __shared__ __align__(16) float ws[128][32];
    __shared__ float xs[32][129];
    const int tid  = threadIdx.x;
    const int row0 = blockIdx.x * 128;

    #pragma unroll 4
    for (int i = tid; i < 128 * 32; i += 128) {
        int k = i >> 5, j = i & 31;
        int g = j >> 3, w = j & 7;
        const float* Wg = (g == 0) ? Wf : (g == 1) ? Wi : (g == 2) ? Wu : Wo;
        ws[k][j] = Wg[k * 8 + w];
    }

    const int lane = tid & 31;
    const int c0   = (tid >> 5) * 8;

    u64 acc[4][4];
    #pragma unroll
    for (int r = 0; r < 4; r++)
        #pragma unroll
        for (int q = 0; q < 4; q++) acc[r][q] = 0ull;

    for (int kc = 0; kc < 4; ++kc) {
        __syncthreads();
        #pragma unroll 4
        for (int i = tid; i < 128 * 32; i += 128) {
            int r = i >> 5, kk = i & 31;
            xs[kk][r] = x[(size_t)(row0 + r) * DIM + kc * 32 + kk];
        }
        __syncthreads();

        #pragma unroll
        for (int k = 0; k < 32; ++k) {
            float xv0 = xs[k][lane      ];
            float xv1 = xs[k][lane + 32 ];
            float xv2 = xs[k][lane + 64 ];
            float xv3 = xs[k][lane + 96 ];
            u64 xx0 = pack2(xv0, xv0);
            u64 xx1 = pack2(xv1, xv1);
            u64 xx2 = pack2(xv2, xv2);
            u64 xx3 = pack2(xv3, xv3);
            const u64* wk = reinterpret_cast<const u64*>(&ws[kc * 32 + k][c0]);
            u64 w0 = wk[0], w1 = wk[1], w2 = wk[2], w3 = wk[3];
            ffma2(acc[0][0], xx0, w0); ffma2(acc[0][1], xx0, w1);
            ffma2(acc[0][2], xx0, w2); ffma2(acc[0][3], xx0, w3);
            ffma2(acc[1][0], xx1, w0); ffma2(acc[1][1], xx1, w1);
            ffma2(acc[1][2], xx1, w2); ffma2(acc[1][3], xx1, w3);
            ffma2(acc[2][0], xx2, w0); ffma2(acc[2][1], xx2, w1);
            ffma2(acc[2][2], xx2, w2); ffma2(acc[2][3], xx2, w3);
            ffma2(acc[3][0], xx3, w0); ffma2(acc[3][1], xx3, w1);
            ffma2(acc[3][2], xx3, w2); ffma2(acc[3][3], xx3, w3);
        }
    }

    #pragma unroll
    for (int rr = 0; rr < 4; ++rr) {
        int r = row0 + lane + 32 * rr;
        u64* dst = reinterpret_cast<u64*>(g_zpre + (size_t)r * NCH + c0);
        dst[0] = acc[rr][0]; dst[1] = acc[rr][1];
        dst[2] = acc[rr][2]; dst[3] = acc[rr][3];
    }
}

// ---------------------------------------------------------------------------
// Kernel B: R4 recurrence with the rotation trick — 17 INDEPENDENT shfls
// per step (was 20). Every shfl sources a plain register with a
// loop-invariant source lane; no shfl-of-shfl, no serial scan.
//   h broadcast:  7 shfls, slot j = h_{(wire+j)&7}; weights pre-permuted.
//   cos gather:   7 shfls, slot j = c_{(wire+j)&7} (own segment);
//                 e_w = c * S_{8-w}, e_0 = S_1, via suffix products.
//   act gather:   3 shfls, slot j = act of gate (gate+j)&3; FSEL mux.
// lane = gate*8 + wire.
// <Z_w> = prod_{k<=w} cos(phi_k) (w>=1), <Z_0> = prod_{k=1..7} cos(phi_k).
// ---------------------------------------------------------------------------
__global__ void __launch_bounds__(128) qlstm_recurrent(
    const float* __restrict__ Wf, const float* __restrict__ bf, const float* __restrict__ thf,
    const float* __restrict__ Wi, const float* __restrict__ bi, const float* __restrict__ thi,
    const float* __restrict__ Wu, const float* __restrict__ bu, const float* __restrict__ thu,
    const float* __restrict__ Wo, const float* __restrict__ bo, const float* __restrict__ tho,
    float* __restrict__ out)
{
    const int lane = threadIdx.x & 31;
    const int warp = threadIdx.x >> 5;
    const int row  = blockIdx.x * 4 + warp;       // 0..511
    const int gate = lane >> 3;
    const int wire = lane & 7;
    const int base = lane & 24;                    // gate*8

    const float* Wg = (gate == 0) ? Wf : (gate == 1) ? Wi : (gate == 2) ? Wu : Wo;
    const float* bg = (gate == 0) ? bf : (gate == 1) ? bi : (gate == 2) ? bu : bo;
    const float* tg = (gate == 0) ? thf : (gate == 1) ? thi : (gate == 2) ? thu : tho;

    // rotated recurrent weights: slot j carries h_{(wire+j)&7}
    float whr[8];
    int hsrc[8];                                   // shfl source lanes (j=1..7)
    int csrc[8];
    #pragma unroll
    for (int j = 0; j < 8; ++j) {
        int kj = (wire + j) & 7;
        whr[j]  = Wg[(DIM + kj) * NQ + wire];
        hsrc[j] = kj;                              // gate-0 lane holding h_kj
        csrc[j] = base + kj;                       // own-segment lane holding c_kj
    }
    // act rotation source lanes (j=1..3): same wire, gate (gate+j)&3
    const int asrc1 = wire + 8 * ((gate + 1) & 3);
    const int asrc2 = wire + 8 * ((gate + 2) & 3);
    const int asrc3 = wire + 8 * ((gate + 3) & 3);

    const float cbias = bg[wire] + tg[wire];
    const bool  isU   = (gate == 2);
    const float aScl  = isU ? 1.0f : 0.5f;
    const float aMul  = isU ? 1.0f : 0.5f;
    const float aAdd  = isU ? 0.0f : 0.5f;

    const bool w0z = (wire == 0);
    const bool b0 = (wire & 1) != 0;
    const bool b1 = (wire & 2) != 0;
    const bool b2 = (wire & 4) != 0;
    const bool gb0 = (gate & 1) != 0;
    const bool gb1 = (gate & 2) != 0;

    float hv = 0.0f, cstate = 0.0f;

    const float* zp = g_zpre + (size_t)row * NCH + lane;
    const size_t tstride = (size_t)BATCH * NCH;
    float zn0 = zp[0];
    float zn1 = zp[tstride];

    float* outw = out + (size_t)row * NQ + wire;   // step stride = BATCH*NQ

    const unsigned FULL = 0xffffffffu;

    #pragma unroll 2
    for (int t = 0; t < T_SEQ; ++t) {
        float zb = zn0 + cbias;
        zn0 = zn1;
        int t2 = (t + 2 < T_SEQ) ? (t + 2) : (T_SEQ - 1);
        zn1 = zp[(size_t)t2 * tstride];             // off-chain prefetch

        // --- h gather: 7 independent shfls (slot 0 = own hv) ---
        float hs1 = __shfl_sync(FULL, hv, hsrc[1]);
        float hs2 = __shfl_sync(FULL, hv, hsrc[2]);
        float hs3 = __shfl_sync(FULL, hv, hsrc[3]);
        float hs4 = __shfl_sync(FULL, hv, hsrc[4]);
        float hs5 = __shfl_sync(FULL, hv, hsrc[5]);
        float hs6 = __shfl_sync(FULL, hv, hsrc[6]);
        float hs7 = __shfl_sync(FULL, hv, hsrc[7]);

        // z = zb + h . wh (rotated order, two parallel FMA chains)
        float za  = fmaf(hv,  whr[0], zb);
        float zc  = hs1 * whr[1];
        za = fmaf(hs2, whr[2], za);
        zc = fmaf(hs3, whr[3], zc);
        za = fmaf(hs4, whr[4], za);
        zc = fmaf(hs5, whr[5], zc);
        za = fmaf(hs6, whr[6], za);
        zc = fmaf(hs7, whr[7], zc);
        float z = za + zc;

        float c = __cosf(z);

        // --- cos gather: 7 independent shfls (slot 0 = own c) ---
        float a1 = __shfl_sync(FULL, c, csrc[1]);
        float a2 = __shfl_sync(FULL, c, csrc[2]);
        float a3 = __shfl_sync(FULL, c, csrc[3]);
        float a4 = __shfl_sync(FULL, c, csrc[4]);
        float a5 = __shfl_sync(FULL, c, csrc[5]);
        float a6 = __shfl_sync(FULL, c, csrc[6]);
        float a7 = __shfl_sync(FULL, c, csrc[7]);

        // suffix products S_m = prod_{j=m..7} slot_j
        float b67 = a6 * a7;
        float b45 = a4 * a5;
        float b23 = a2 * a3;
        float S7 = a7;
        float S6 = b67;
        float S5 = a5 * b67;
        float S4 = b45 * b67;
        float S3 = a3 * S4;
        float S2 = b23 * S4;
        float S1 = a1 * S2;

        // select S_{8-wire} (wire>=1) / S_1 (wire==0,7): vals by wire =
        //   {S1, S7, S6, S5, S4, S3, S2, S1}
        float m00 = b0 ? S7 : S1;
        float m01 = b0 ? S5 : S6;
        float m10 = b0 ? S3 : S4;
        float m11 = b0 ? S1 : S2;
        float n0  = b1 ? m01 : m00;
        float n1  = b1 ? m11 : m10;
        float sel = b2 ? n1 : n0;

        float e = w0z ? sel : c * sel;              // <Z_wire>

        // activation: sigmoid via tanh for f,i,o; tanh for u
        float act = fmaf(aMul, tanh_approx(e * aScl), aAdd);

        // --- act gather: 3 independent shfls (slot 0 = own act) ---
        float v1 = __shfl_sync(FULL, act, asrc1);   // gate (g+1)&3
        float v2 = __shfl_sync(FULL, act, asrc2);   // gate (g+2)&3
        float v3 = __shfl_sync(FULL, act, asrc3);   // gate (g+3)&3

        // mux f/i/u/o: slot j holds gate (g+j)&3; need gate 0/1/2/3
        float fv = gb1 ? (gb0 ? v1  : v2) : (gb0 ? v3  : act);
        float iv = gb1 ? (gb0 ? v2  : v3) : (gb0 ? act : v1);
        float uv = gb1 ? (gb0 ? v3  : act) : (gb0 ? v1  : v2);
        float ov = gb1 ? (gb0 ? act : v1) : (gb0 ? v2  : v3);

        cstate = fmaf(fv, cstate, iv * uv);
        hv     = ov * tanh_approx(cstate);

        if (lane < 8)
            outw[(size_t)t * (BATCH * NQ)] = hv;     // predicated store
    }

    if (lane < 8) {
        const size_t outs_sz = (size_t)T_SEQ * BATCH * NQ;
        out[outs_sz + (size_t)row * NQ + wire] = hv;                           // final hx
        out[outs_sz + (size_t)BATCH * NQ + (size_t)row * NQ + wire] = cstate;  // final cx
    }
}

// ---------------------------------------------------------------------------
// Launch (R4 structure)
// ---------------------------------------------------------------------------
extern "C" void kernel_launch(void* const* d_in, const int* in_sizes, int n_in,
                              void* d_out, int out_size)
{
    const float* x   = (const float*)d_in[0];
    const float* Wf  = (const float*)d_in[1];
    const float* bf  = (const float*)d_in[2];
    const float* thf = (const float*)d_in[3];
    const float* Wi  = (const float*)d_in[4];
    const float* bi  = (const float*)d_in[5];
    const float* thi = (const float*)d_in[6];
    const float* Wu  = (const float*)d_in[7];
    const float* bu  = (const float*)d_in[8];
    const float* thu = (const float*)d_in[9];
    const float* Wo  = (const float*)d_in[10];
    const float* bo  = (const float*)d_in[11];
    const float* tho = (const float*)d_in[12];
    float* out = (float*)d_out;

    qlstm_gemm<<<(T_SEQ * BATCH) / 128, 128>>>(x, Wf, Wi, Wu, Wo);
    qlstm_recurrent<<<BATCH / 4, 128>>>(Wf, bf, thf, Wi, bi, thi,
                                        Wu, bu, thu, Wo, bo, tho, out);
}